// round 15
// baseline (speedup 1.0000x reference)
#include <cuda_runtime.h>
#include <cuda_fp16.h>
#include <cstdint>

#define BATCH 4
#define SEQ   4096
#define DM    1024
#define DF    64
#define ROWS  (BATCH * SEQ)   // 16384

// Projected tensors in fp16: g_q (pre-scaled by 1/8), g_k, g_vt (transposed [b][f][s])
__device__ __half g_q[(size_t)ROWS * DF];
__device__ __half g_k[(size_t)ROWS * DF];
__device__ __half g_vt[(size_t)BATCH * DF * SEQ];

// ---------------------------------------------------------------------------
// helpers
// ---------------------------------------------------------------------------
__device__ __forceinline__ uint32_t pack_h2(float lo, float hi) {
    __half2 h = __floats2half2_rn(lo, hi);
    return *(uint32_t*)&h;
}

__device__ __forceinline__ void mma_f16(float* d, const uint32_t* a,
                                        uint32_t b0, uint32_t b1) {
    asm volatile(
        "mma.sync.aligned.m16n8k16.row.col.f32.f16.f16.f32 "
        "{%0,%1,%2,%3}, {%4,%5,%6,%7}, {%8,%9}, {%0,%1,%2,%3};"
        : "+f"(d[0]), "+f"(d[1]), "+f"(d[2]), "+f"(d[3])
        : "r"(a[0]), "r"(a[1]), "r"(a[2]), "r"(a[3]), "r"(b0), "r"(b1));
}

__device__ __forceinline__ void ldsm_x4(uint32_t* r, uint32_t addr) {
    asm volatile("ldmatrix.sync.aligned.m8n8.x4.shared.b16 {%0,%1,%2,%3}, [%4];"
        : "=r"(r[0]), "=r"(r[1]), "=r"(r[2]), "=r"(r[3]) : "r"(addr));
}

__device__ __forceinline__ uint32_t smem_u32(const void* p) {
    uint32_t a;
    asm("{ .reg .u64 t; cvta.to.shared.u64 t, %1; cvt.u32.u64 %0, t; }"
        : "=r"(a) : "l"(p));
    return a;
}
__device__ __forceinline__ void cp_async16(uint32_t dst, const void* src) {
    asm volatile("cp.async.cg.shared.global [%0], [%1], 16;"
                 :: "r"(dst), "l"(src) : "memory");
}
#define CP_COMMIT() asm volatile("cp.async.commit_group;" ::: "memory")
#define CP_WAIT0()  asm volatile("cp.async.wait_group 0;" ::: "memory")
#define CP_WAIT1()  asm volatile("cp.async.wait_group 1;" ::: "memory")

// ---------------------------------------------------------------------------
// Projection (fp16 mma m16n8k16): BM=128, BN=64, BK=32, 256 thr, 8 warps,
// occupancy 3 -> grid 384 fits in ONE wave (444 slots).
// UNIFORM work for all z (no V split; fp16 rounding noise ~2e-4 is in budget).
// Double-buffered smem, one sync/iter: MMA(buf) -> STS(next) -> sync -> LDG.
// Epilogue: Q(x1/8)/K fp16; V fp16 TRANSPOSED via fp32 smem scratch.
// ---------------------------------------------------------------------------
#define XSTB 80u                 // bytes per 32-half row (stride 40 halves)
#define STG_B 15360u             // per-stage: XH 10240 + WH 5120
#define XH_O 0u
#define WH_O 10240u
#define P_BYTES 33792            // max(2 stages = 30720, V-transpose 33792)
#define VTS 132                  // V-transpose fp32 smem stride (words)

__global__ void __launch_bounds__(256, 3) proj_tc_kernel(
    const float* __restrict__ q_in, const float* __restrict__ k_in,
    const float* __restrict__ v_in,
    const float* __restrict__ Wq, const float* __restrict__ bq,
    const float* __restrict__ Wk, const float* __restrict__ bk,
    const float* __restrict__ Wv, const float* __restrict__ bv)
{
    extern __shared__ float sm[];
    const uint32_t sb = smem_u32(sm);

    const int z  = blockIdx.x % 3;
    const int R0 = (blockIdx.x / 3) * 128;
    const float* X    = (z == 0) ? q_in : (z == 1) ? k_in : v_in;
    const float* W    = (z == 0) ? Wq   : (z == 1) ? Wk   : Wv;
    const float* bias = (z == 0) ? bq   : (z == 1) ? bk   : bv;

    const int tid  = threadIdx.x;
    const int w    = tid >> 5;
    const int lane = tid & 31;
    const int gid  = lane >> 2;
    const int tig  = lane & 3;
    const int rg   = w & 3;          // rows rg*32 .. +32
    const int ch   = w >> 2;         // cols ch*32 .. +32

    const float4* Xg = (const float4*)X;
    const float4* Wg = (const float4*)W;
    const int xrow = tid >> 3, xc4 = tid & 7;

    // ldmatrix per-lane offsets (within a stage)
    const int lm = lane >> 3, lr = lane & 7;
    const uint32_t xa_off = (uint32_t)(((lm & 1) * 8 + lr) * 80 + (lm >> 1) * 16)
                          + (uint32_t)rg * 32u * 80u;
    const uint32_t wb_off = (uint32_t)(((lm >> 1) * 8 + lr) * 80 + (lm & 1) * 16)
                          + (uint32_t)ch * 32u * 80u;

    float acc[2][4][4];
#pragma unroll
    for (int t = 0; t < 2; t++)
#pragma unroll
        for (int nt = 0; nt < 4; nt++)
#pragma unroll
            for (int j = 0; j < 4; j++) acc[t][nt][j] = 0.f;

    float4 xr[4], wr[2];

#define PROJ_STS(SBASE)                                                        \
    do {                                                                       \
        _Pragma("unroll")                                                      \
        for (int i = 0; i < 4; i++) {                                          \
            int row = xrow + i * 32;                                           \
            uint32_t off = (uint32_t)row * XSTB + (uint32_t)xc4 * 8u;          \
            float4 v = xr[i];                                                  \
            __half2 h01 = __floats2half2_rn(v.x, v.y);                         \
            __half2 h23 = __floats2half2_rn(v.z, v.w);                         \
            *(uint2*)((char*)sm + (SBASE) + XH_O + off) =                      \
                make_uint2(*(uint32_t*)&h01, *(uint32_t*)&h23);                \
        }                                                                      \
        _Pragma("unroll")                                                      \
        for (int i = 0; i < 2; i++) {                                          \
            int row = xrow + i * 32;                                           \
            uint32_t off = (uint32_t)row * XSTB + (uint32_t)xc4 * 8u;          \
            float4 v = wr[i];                                                  \
            __half2 h01 = __floats2half2_rn(v.x, v.y);                         \
            __half2 h23 = __floats2half2_rn(v.z, v.w);                         \
            *(uint2*)((char*)sm + (SBASE) + WH_O + off) =                      \
                make_uint2(*(uint32_t*)&h01, *(uint32_t*)&h23);                \
        }                                                                      \
    } while (0)

#define PROJ_LDG(IT)                                                           \
    do {                                                                       \
        const int m4 = (IT) * 8;                                               \
        _Pragma("unroll")                                                      \
        for (int i = 0; i < 4; i++)                                            \
            xr[i] = Xg[(size_t)(R0 + xrow + i * 32) * 256 + m4 + xc4];         \
        _Pragma("unroll")                                                      \
        for (int i = 0; i < 2; i++)                                            \
            wr[i] = Wg[(size_t)(xrow + i * 32) * 256 + m4 + xc4];              \
    } while (0)

    PROJ_LDG(0);
    PROJ_STS(0u);
    __syncthreads();
    PROJ_LDG(1);

    for (int it = 0; it < 32; it++) {
        const uint32_t sbase = sb + (uint32_t)(it & 1) * STG_B;

#pragma unroll
        for (int ks = 0; ks < 2; ks++) {
            const uint32_t ko = (uint32_t)ks * 32u;
            uint32_t a[2][4], bfr[2][4];
            ldsm_x4(a[0],   sbase + XH_O + xa_off + ko);
            ldsm_x4(a[1],   sbase + XH_O + xa_off + 1280u + ko);
            ldsm_x4(bfr[0], sbase + WH_O + wb_off + ko);
            ldsm_x4(bfr[1], sbase + WH_O + wb_off + 1280u + ko);
#pragma unroll
            for (int t = 0; t < 2; t++)
#pragma unroll
                for (int p = 0; p < 2; p++) {
                    mma_f16(acc[t][2 * p],     a[t], bfr[p][0], bfr[p][1]);
                    mma_f16(acc[t][2 * p + 1], a[t], bfr[p][2], bfr[p][3]);
                }
        }

        if (it + 1 < 32) {
            PROJ_STS((uint32_t)((it + 1) & 1) * STG_B);
            __syncthreads();
            if (it + 2 < 32) PROJ_LDG(it + 2);
        }
    }

    // ---- epilogue ----
    if (z == 0) {
        uint32_t* gq = (uint32_t*)g_q;
#pragma unroll
        for (int t = 0; t < 2; t++) {
            int r = rg * 32 + t * 16 + gid;
#pragma unroll
            for (int nt = 0; nt < 4; nt++) {
                int col = ch * 32 + nt * 8 + 2 * tig;
                float2 bb = *(const float2*)&bias[col];
                gq[(size_t)(R0 + r) * 32 + (col >> 1)] =
                    pack_h2((acc[t][nt][0] + bb.x) * 0.125f,
                            (acc[t][nt][1] + bb.y) * 0.125f);
                gq[(size_t)(R0 + r + 8) * 32 + (col >> 1)] =
                    pack_h2((acc[t][nt][2] + bb.x) * 0.125f,
                            (acc[t][nt][3] + bb.y) * 0.125f);
            }
        }
    } else if (z == 1) {
        uint32_t* gk = (uint32_t*)g_k;
#pragma unroll
        for (int t = 0; t < 2; t++) {
            int r = rg * 32 + t * 16 + gid;
#pragma unroll
            for (int nt = 0; nt < 4; nt++) {
                int col = ch * 32 + nt * 8 + 2 * tig;
                float2 bb = *(const float2*)&bias[col];
                gk[(size_t)(R0 + r) * 32 + (col >> 1)] =
                    pack_h2(acc[t][nt][0] + bb.x, acc[t][nt][1] + bb.y);
                gk[(size_t)(R0 + r + 8) * 32 + (col >> 1)] =
                    pack_h2(acc[t][nt][2] + bb.x, acc[t][nt][3] + bb.y);
            }
        }
    } else {
        // V: fp32 transpose through smem, then packed fp16 coalesced stores.
        __syncthreads();
        float* T = sm;   // [64 f][VTS]
#pragma unroll
        for (int t = 0; t < 2; t++) {
            int s = rg * 32 + t * 16 + gid;
#pragma unroll
            for (int nt = 0; nt < 4; nt++) {
                int col = ch * 32 + nt * 8 + 2 * tig;
                float2 bb = *(const float2*)&bias[col];
                T[(col)     * VTS + s]     = acc[t][nt][0] + bb.x;
                T[(col + 1) * VTS + s]     = acc[t][nt][1] + bb.y;
                T[(col)     * VTS + s + 8] = acc[t][nt][2] + bb.x;
                T[(col + 1) * VTS + s + 8] = acc[t][nt][3] + bb.y;
            }
        }
        __syncthreads();
        const int bb = R0 >> 12;
        const int s0 = R0 & 4095;
        __half* vt = g_vt + (size_t)bb * DF * SEQ + s0;
#pragma unroll
        for (int i = 0; i < 4; i++) {
            int idx = tid + i * 256;         // 64 f x 16 s-groups
            int f = idx >> 4, sg = idx & 15;
            const float* src = T + f * VTS + sg * 8;
            uint4 u;
            u.x = pack_h2(src[0], src[1]);
            u.y = pack_h2(src[2], src[3]);
            u.z = pack_h2(src[4], src[5]);
            u.w = pack_h2(src[6], src[7]);
            *(uint4*)(vt + (size_t)f * SEQ + sg * 8) = u;
        }
    }
}

// ---------------------------------------------------------------------------
// Attention (fp16 m16n8k16): 256 threads, 8 warps = 4 q-groups (64 rows/CTA)
// x 2 key-halves -> grid 256 CTAs, 2 CTAs/SM, all 148 SMs busy.
// All B-fragments via ldmatrix.x4; PV A-frags = cvt-packed exp(S) C-frags.
// 3 fp16 K/V smem buffers via cp.async, 1 sync/tile. No max-subtraction
// softmax; O in fp32 regs; key halves merge through smem at the end.
// ---------------------------------------------------------------------------
#define KV_BYTES 32768u                   // K(128x64 h) + V(64x128 h)
#define A_BYTES  (3 * 32768)              // 98304

__device__ __forceinline__ void stage_tile(uint32_t kb, uint32_t vb,
                                           const __half* __restrict__ gk_tile,
                                           const __half* __restrict__ gvt_b,
                                           int kt0, int tid)
{
#pragma unroll
    for (int i = 0; i < 4; i++) {
        int idx = tid + i * 256;            // 0..1023
        int row = idx >> 3, g = idx & 7;
        uint32_t dst = kb + (uint32_t)row * 128u + (uint32_t)((g ^ (row & 7)) << 4);
        cp_async16(dst, gk_tile + (size_t)row * 64 + g * 8);
    }
#pragma unroll
    for (int i = 0; i < 4; i++) {
        int idx = tid + i * 256;
        int row = idx >> 4, g = idx & 15;
        uint32_t dst = vb + (uint32_t)row * 256u + (uint32_t)((g ^ (row & 15)) << 4);
        cp_async16(dst, gvt_b + (size_t)row * SEQ + kt0 + g * 8);
    }
}

__global__ void __launch_bounds__(256, 2) attn_mma_kernel(float* __restrict__ out)
{
    extern __shared__ float sm[];
    const uint32_t sb = smem_u32(sm);

    const int tid  = threadIdx.x;
    const int w    = tid >> 5;
    const int lane = tid & 31;
    const int gid  = lane >> 2;
    const int tig  = lane & 3;
    const int wq   = w & 3;          // q-row group (16 rows)
    const int h    = w >> 2;         // key half (64 keys)
    const int b    = blockIdx.y;
    const int q0   = blockIdx.x * 64;
    const int r0   = wq * 16 + gid;  // rows r0, r0+8 (local)

    // ldmatrix lane decomposition
    const int lr = lane & 7;
    const int gi = lane >> 3;
    const uint32_t k_row = (uint32_t)(h * 64 + lr) * 128u;
    const uint32_t kgA = (uint32_t)((gi ^ lr) << 4);
    const uint32_t kgB = (uint32_t)(((gi + 4) ^ lr) << 4);
    const int fl = ((gi >> 1) << 3) + lr;
    const uint32_t v_row = (uint32_t)fl * 256u;

    // ---- Q A-frags straight from fp16 global ----
    const uint32_t* gq = (const uint32_t*)g_q + ((size_t)b * SEQ + q0) * 32;
    uint32_t qa[4][4];
#pragma unroll
    for (int kc = 0; kc < 4; kc++) {
        qa[kc][0] = gq[(size_t)r0 * 32 + kc * 8 + tig];
        qa[kc][1] = gq[(size_t)(r0 + 8) * 32 + kc * 8 + tig];
        qa[kc][2] = gq[(size_t)r0 * 32 + kc * 8 + tig + 4];
        qa[kc][3] = gq[(size_t)(r0 + 8) * 32 + kc * 8 + tig + 4];
    }

    float o[8][4];
#pragma unroll
    for (int ft = 0; ft < 8; ft++)
#pragma unroll
        for (int j = 0; j < 4; j++) o[ft][j] = 0.f;
    float lsum0 = 0.f, lsum1 = 0.f;

    const __half* gk_base = g_k + (size_t)b * SEQ * DF;
    const __half* gvt_b   = g_vt + (size_t)b * DF * SEQ;

    stage_tile(sb, sb + 16384u, gk_base, gvt_b, 0, tid);
    CP_COMMIT();
    stage_tile(sb + KV_BYTES, sb + KV_BYTES + 16384u,
               gk_base + 128 * 64, gvt_b, 128, tid);
    CP_COMMIT();

    for (int t = 0; t < SEQ / 128; t++) {
        if (t + 1 < SEQ / 128) { CP_WAIT1(); } else { CP_WAIT0(); }
        __syncthreads();
        if (t + 2 < SEQ / 128) {
            uint32_t kb = sb + (uint32_t)((t + 2) % 3) * KV_BYTES;
            stage_tile(kb, kb + 16384u,
                       gk_base + (size_t)(t + 2) * 128 * 64, gvt_b,
                       (t + 2) * 128, tid);
            CP_COMMIT();
        }

        const uint32_t Kp = sb + (uint32_t)(t % 3) * KV_BYTES;
        const uint32_t Vp = Kp + 16384u;

#pragma unroll
        for (int j = 0; j < 4; j++) {        // 16-key chunks
            uint32_t pa[4];
#pragma unroll
            for (int hn = 0; hn < 2; hn++) {
                const int nt = j * 2 + hn;
                const uint32_t kbse = Kp + k_row + (uint32_t)nt * 1024u;
                uint32_t ra[4], rb[4];
                ldsm_x4(ra, kbse + kgA);
                ldsm_x4(rb, kbse + kgB);
                float s0[4] = {0.f, 0.f, 0.f, 0.f};
                float s1[4] = {0.f, 0.f, 0.f, 0.f};
                mma_f16(s0, qa[0], ra[0], ra[1]);
                mma_f16(s1, qa[1], ra[2], ra[3]);
                mma_f16(s0, qa[2], rb[0], rb[1]);
                mma_f16(s1, qa[3], rb[2], rb[3]);
                float e0 = __expf(s0[0] + s1[0]);
                float e1 = __expf(s0[1] + s1[1]);
                float e2 = __expf(s0[2] + s1[2]);
                float e3 = __expf(s0[3] + s1[3]);
                lsum0 += e0 + e1;
                lsum1 += e2 + e3;
                pa[hn * 2]     = pack_h2(e0, e1);
                pa[hn * 2 + 1] = pack_h2(e2, e3);
            }
            const uint32_t gx =
                (uint32_t)(((h * 8 + j * 2 + (gi & 1)) ^ fl) << 4);
#pragma unroll
            for (int ftp = 0; ftp < 4; ftp++) {
                uint32_t rv[4];
                ldsm_x4(rv, Vp + v_row + (uint32_t)ftp * 4096u + gx);
                mma_f16(o[ftp * 2],     pa, rv[0], rv[1]);
                mma_f16(o[ftp * 2 + 1], pa, rv[2], rv[3]);
            }
        }
    }

    // ---- quad-reduce l, merge the two key halves through smem ----
    lsum0 += __shfl_xor_sync(0xFFFFFFFF, lsum0, 1);
    lsum0 += __shfl_xor_sync(0xFFFFFFFF, lsum0, 2);
    lsum1 += __shfl_xor_sync(0xFFFFFFFF, lsum1, 1);
    lsum1 += __shfl_xor_sync(0xFFFFFFFF, lsum1, 2);

    __syncthreads();
    float* M  = sm;            // partial O: 64 x 64 fp32
    float* Lm = sm + 4096;     // partial l: 64
    if (h == 1) {
        Lm[r0]     = lsum0;
        Lm[r0 + 8] = lsum1;
#pragma unroll
        for (int ft = 0; ft < 8; ft++) {
            float2 u0, u1;
            u0.x = o[ft][0]; u0.y = o[ft][1];
            u1.x = o[ft][2]; u1.y = o[ft][3];
            *(float2*)(M + (r0)     * 64 + ft * 8 + 2 * tig) = u0;
            *(float2*)(M + (r0 + 8) * 64 + ft * 8 + 2 * tig) = u1;
        }
    }
    __syncthreads();
    if (h == 0) {
        const float inv0 = 1.f / (lsum0 + Lm[r0]);
        const float inv1 = 1.f / (lsum1 + Lm[r0 + 8]);
        float* og0 = out + ((size_t)b * SEQ + q0 + r0) * DF;
        float* og1 = og0 + 8 * DF;
#pragma unroll
        for (int ft = 0; ft < 8; ft++) {
            float2 p0 = *(float2*)(M + (r0)     * 64 + ft * 8 + 2 * tig);
            float2 p1 = *(float2*)(M + (r0 + 8) * 64 + ft * 8 + 2 * tig);
            float2 u0, u1;
            u0.x = (o[ft][0] + p0.x) * inv0;
            u0.y = (o[ft][1] + p0.y) * inv0;
            u1.x = (o[ft][2] + p1.x) * inv1;
            u1.y = (o[ft][3] + p1.y) * inv1;
            *(float2*)(og0 + ft * 8 + 2 * tig) = u0;
            *(float2*)(og1 + ft * 8 + 2 * tig) = u1;
        }
    }
}

// ---------------------------------------------------------------------------
extern "C" void kernel_launch(void* const* d_in, const int* in_sizes, int n_in,
                              void* d_out, int out_size)
{
    const float* queries = (const float*)d_in[0];
    const float* keys    = (const float*)d_in[1];
    const float* values  = (const float*)d_in[2];
    const float* Wq      = (const float*)d_in[3];
    const float* bq      = (const float*)d_in[4];
    const float* Wk      = (const float*)d_in[5];
    const float* bk      = (const float*)d_in[6];
    const float* Wv      = (const float*)d_in[7];
    const float* bv      = (const float*)d_in[8];
    float* out = (float*)d_out;

    static bool attr_set = false;
    if (!attr_set) {
        cudaFuncSetAttribute(proj_tc_kernel,
                             cudaFuncAttributeMaxDynamicSharedMemorySize, P_BYTES);
        cudaFuncSetAttribute(attn_mma_kernel,
                             cudaFuncAttributeMaxDynamicSharedMemorySize, A_BYTES);
        attr_set = true;
    }

    dim3 pgrid(3 * ROWS / 128, 1, 1);
    proj_tc_kernel<<<pgrid, 256, P_BYTES>>>(queries, keys, values,
                                            Wq, bq, Wk, bk, Wv, bv);

    dim3 agrid(SEQ / 64, BATCH, 1);
    attn_mma_kernel<<<agrid, 256, A_BYTES>>>(out);
}

// round 16
// speedup vs baseline: 1.0061x; 1.0061x over previous
#include <cuda_runtime.h>
#include <cuda_fp16.h>
#include <cstdint>

#define BATCH 4
#define SEQ   4096
#define DM    1024
#define DF    64
#define ROWS  (BATCH * SEQ)   // 16384

// Projected tensors in fp16: g_q (pre-scaled by 1/8), g_k, g_vt (transposed [b][f][s])
__device__ __half g_q[(size_t)ROWS * DF];
__device__ __half g_k[(size_t)ROWS * DF];
__device__ __half g_vt[(size_t)BATCH * DF * SEQ];

// ---------------------------------------------------------------------------
// helpers
// ---------------------------------------------------------------------------
__device__ __forceinline__ uint32_t pack_h2(float lo, float hi) {
    __half2 h = __floats2half2_rn(lo, hi);
    return *(uint32_t*)&h;
}

__device__ __forceinline__ void mma_f16(float* d, const uint32_t* a,
                                        uint32_t b0, uint32_t b1) {
    asm volatile(
        "mma.sync.aligned.m16n8k16.row.col.f32.f16.f16.f32 "
        "{%0,%1,%2,%3}, {%4,%5,%6,%7}, {%8,%9}, {%0,%1,%2,%3};"
        : "+f"(d[0]), "+f"(d[1]), "+f"(d[2]), "+f"(d[3])
        : "r"(a[0]), "r"(a[1]), "r"(a[2]), "r"(a[3]), "r"(b0), "r"(b1));
}

__device__ __forceinline__ void ldsm_x4(uint32_t* r, uint32_t addr) {
    asm volatile("ldmatrix.sync.aligned.m8n8.x4.shared.b16 {%0,%1,%2,%3}, [%4];"
        : "=r"(r[0]), "=r"(r[1]), "=r"(r[2]), "=r"(r[3]) : "r"(addr));
}

__device__ __forceinline__ uint32_t smem_u32(const void* p) {
    uint32_t a;
    asm("{ .reg .u64 t; cvta.to.shared.u64 t, %1; cvt.u32.u64 %0, t; }"
        : "=r"(a) : "l"(p));
    return a;
}
__device__ __forceinline__ void cp_async16(uint32_t dst, const void* src) {
    asm volatile("cp.async.cg.shared.global [%0], [%1], 16;"
                 :: "r"(dst), "l"(src) : "memory");
}
#define CP_COMMIT() asm volatile("cp.async.commit_group;" ::: "memory")
#define CP_WAIT0()  asm volatile("cp.async.wait_group 0;" ::: "memory")
#define CP_WAIT1()  asm volatile("cp.async.wait_group 1;" ::: "memory")

// ---------------------------------------------------------------------------
// Projection (fp16 mma m16n8k16): BM=128, BN=64, BK=32, 256 thr, 8 warps,
// occupancy 3 -> grid 384 fits in ONE wave (444 slots).
// UNIFORM work for all z (no V split; fp16 rounding noise ~2e-4 is in budget).
// Double-buffered smem, one sync/iter: MMA(buf) -> STS(next) -> sync -> LDG.
// Epilogue: Q(x1/8)/K fp16; V fp16 TRANSPOSED via fp32 smem scratch.
// ---------------------------------------------------------------------------
#define XSTB 80u                 // bytes per 32-half row (stride 40 halves)
#define STG_B 15360u             // per-stage: XH 10240 + WH 5120
#define XH_O 0u
#define WH_O 10240u
#define P_BYTES 33792            // max(2 stages = 30720, V-transpose 33792)
#define VTS 132                  // V-transpose fp32 smem stride (words)

__global__ void __launch_bounds__(256, 3) proj_tc_kernel(
    const float* __restrict__ q_in, const float* __restrict__ k_in,
    const float* __restrict__ v_in,
    const float* __restrict__ Wq, const float* __restrict__ bq,
    const float* __restrict__ Wk, const float* __restrict__ bk,
    const float* __restrict__ Wv, const float* __restrict__ bv)
{
    extern __shared__ float sm[];
    const uint32_t sb = smem_u32(sm);

    const int z  = blockIdx.x % 3;
    const int R0 = (blockIdx.x / 3) * 128;
    const float* X    = (z == 0) ? q_in : (z == 1) ? k_in : v_in;
    const float* W    = (z == 0) ? Wq   : (z == 1) ? Wk   : Wv;
    const float* bias = (z == 0) ? bq   : (z == 1) ? bk   : bv;

    const int tid  = threadIdx.x;
    const int w    = tid >> 5;
    const int lane = tid & 31;
    const int gid  = lane >> 2;
    const int tig  = lane & 3;
    const int rg   = w & 3;          // rows rg*32 .. +32
    const int ch   = w >> 2;         // cols ch*32 .. +32

    const float4* Xg = (const float4*)X;
    const float4* Wg = (const float4*)W;
    const int xrow = tid >> 3, xc4 = tid & 7;

    // ldmatrix per-lane offsets (within a stage)
    const int lm = lane >> 3, lr = lane & 7;
    const uint32_t xa_off = (uint32_t)(((lm & 1) * 8 + lr) * 80 + (lm >> 1) * 16)
                          + (uint32_t)rg * 32u * 80u;
    const uint32_t wb_off = (uint32_t)(((lm >> 1) * 8 + lr) * 80 + (lm & 1) * 16)
                          + (uint32_t)ch * 32u * 80u;

    float acc[2][4][4];
#pragma unroll
    for (int t = 0; t < 2; t++)
#pragma unroll
        for (int nt = 0; nt < 4; nt++)
#pragma unroll
            for (int j = 0; j < 4; j++) acc[t][nt][j] = 0.f;

    float4 xr[4], wr[2];

#define PROJ_STS(SBASE)                                                        \
    do {                                                                       \
        _Pragma("unroll")                                                      \
        for (int i = 0; i < 4; i++) {                                          \
            int row = xrow + i * 32;                                           \
            uint32_t off = (uint32_t)row * XSTB + (uint32_t)xc4 * 8u;          \
            float4 v = xr[i];                                                  \
            __half2 h01 = __floats2half2_rn(v.x, v.y);                         \
            __half2 h23 = __floats2half2_rn(v.z, v.w);                         \
            *(uint2*)((char*)sm + (SBASE) + XH_O + off) =                      \
                make_uint2(*(uint32_t*)&h01, *(uint32_t*)&h23);                \
        }                                                                      \
        _Pragma("unroll")                                                      \
        for (int i = 0; i < 2; i++) {                                          \
            int row = xrow + i * 32;                                           \
            uint32_t off = (uint32_t)row * XSTB + (uint32_t)xc4 * 8u;          \
            float4 v = wr[i];                                                  \
            __half2 h01 = __floats2half2_rn(v.x, v.y);                         \
            __half2 h23 = __floats2half2_rn(v.z, v.w);                         \
            *(uint2*)((char*)sm + (SBASE) + WH_O + off) =                      \
                make_uint2(*(uint32_t*)&h01, *(uint32_t*)&h23);                \
        }                                                                      \
    } while (0)

#define PROJ_LDG(IT)                                                           \
    do {                                                                       \
        const int m4 = (IT) * 8;                                               \
        _Pragma("unroll")                                                      \
        for (int i = 0; i < 4; i++)                                            \
            xr[i] = Xg[(size_t)(R0 + xrow + i * 32) * 256 + m4 + xc4];         \
        _Pragma("unroll")                                                      \
        for (int i = 0; i < 2; i++)                                            \
            wr[i] = Wg[(size_t)(xrow + i * 32) * 256 + m4 + xc4];              \
    } while (0)

    PROJ_LDG(0);
    PROJ_STS(0u);
    __syncthreads();
    PROJ_LDG(1);

    for (int it = 0; it < 32; it++) {
        const uint32_t sbase = sb + (uint32_t)(it & 1) * STG_B;

#pragma unroll
        for (int ks = 0; ks < 2; ks++) {
            const uint32_t ko = (uint32_t)ks * 32u;
            uint32_t a[2][4], bfr[2][4];
            ldsm_x4(a[0],   sbase + XH_O + xa_off + ko);
            ldsm_x4(a[1],   sbase + XH_O + xa_off + 1280u + ko);
            ldsm_x4(bfr[0], sbase + WH_O + wb_off + ko);
            ldsm_x4(bfr[1], sbase + WH_O + wb_off + 1280u + ko);
#pragma unroll
            for (int t = 0; t < 2; t++)
#pragma unroll
                for (int p = 0; p < 2; p++) {
                    mma_f16(acc[t][2 * p],     a[t], bfr[p][0], bfr[p][1]);
                    mma_f16(acc[t][2 * p + 1], a[t], bfr[p][2], bfr[p][3]);
                }
        }

        if (it + 1 < 32) {
            PROJ_STS((uint32_t)((it + 1) & 1) * STG_B);
            __syncthreads();
            if (it + 2 < 32) PROJ_LDG(it + 2);
        }
    }

    // ---- epilogue ----
    if (z == 0) {
        uint32_t* gq = (uint32_t*)g_q;
#pragma unroll
        for (int t = 0; t < 2; t++) {
            int r = rg * 32 + t * 16 + gid;
#pragma unroll
            for (int nt = 0; nt < 4; nt++) {
                int col = ch * 32 + nt * 8 + 2 * tig;
                float2 bb = *(const float2*)&bias[col];
                gq[(size_t)(R0 + r) * 32 + (col >> 1)] =
                    pack_h2((acc[t][nt][0] + bb.x) * 0.125f,
                            (acc[t][nt][1] + bb.y) * 0.125f);
                gq[(size_t)(R0 + r + 8) * 32 + (col >> 1)] =
                    pack_h2((acc[t][nt][2] + bb.x) * 0.125f,
                            (acc[t][nt][3] + bb.y) * 0.125f);
            }
        }
    } else if (z == 1) {
        uint32_t* gk = (uint32_t*)g_k;
#pragma unroll
        for (int t = 0; t < 2; t++) {
            int r = rg * 32 + t * 16 + gid;
#pragma unroll
            for (int nt = 0; nt < 4; nt++) {
                int col = ch * 32 + nt * 8 + 2 * tig;
                float2 bb = *(const float2*)&bias[col];
                gk[(size_t)(R0 + r) * 32 + (col >> 1)] =
                    pack_h2(acc[t][nt][0] + bb.x, acc[t][nt][1] + bb.y);
                gk[(size_t)(R0 + r + 8) * 32 + (col >> 1)] =
                    pack_h2(acc[t][nt][2] + bb.x, acc[t][nt][3] + bb.y);
            }
        }
    } else {
        // V: fp32 transpose through smem, then packed fp16 coalesced stores.
        __syncthreads();
        float* T = sm;   // [64 f][VTS]
#pragma unroll
        for (int t = 0; t < 2; t++) {
            int s = rg * 32 + t * 16 + gid;
#pragma unroll
            for (int nt = 0; nt < 4; nt++) {
                int col = ch * 32 + nt * 8 + 2 * tig;
                float2 bb = *(const float2*)&bias[col];
                T[(col)     * VTS + s]     = acc[t][nt][0] + bb.x;
                T[(col + 1) * VTS + s]     = acc[t][nt][1] + bb.y;
                T[(col)     * VTS + s + 8] = acc[t][nt][2] + bb.x;
                T[(col + 1) * VTS + s + 8] = acc[t][nt][3] + bb.y;
            }
        }
        __syncthreads();
        const int bb = R0 >> 12;
        const int s0 = R0 & 4095;
        __half* vt = g_vt + (size_t)bb * DF * SEQ + s0;
#pragma unroll
        for (int i = 0; i < 4; i++) {
            int idx = tid + i * 256;         // 64 f x 16 s-groups
            int f = idx >> 4, sg = idx & 15;
            const float* src = T + f * VTS + sg * 8;
            uint4 u;
            u.x = pack_h2(src[0], src[1]);
            u.y = pack_h2(src[2], src[3]);
            u.z = pack_h2(src[4], src[5]);
            u.w = pack_h2(src[6], src[7]);
            *(uint4*)(vt + (size_t)f * SEQ + sg * 8) = u;
        }
    }
}

// ---------------------------------------------------------------------------
// Attention (fp16 m16n8k16): 256 threads, 8 warps = 4 q-groups (64 rows/CTA)
// x 2 key-halves -> grid 256 CTAs, 2 CTAs/SM, all 148 SMs busy.
// All B-fragments via ldmatrix.x4; PV A-frags = cvt-packed exp(S) C-frags.
// 3 fp16 K/V smem buffers via cp.async, 1 sync/tile. No max-subtraction
// softmax; O in fp32 regs; key halves merge through smem at the end.
// ---------------------------------------------------------------------------
#define KV_BYTES 32768u                   // K(128x64 h) + V(64x128 h)
#define A_BYTES  (3 * 32768)              // 98304

__device__ __forceinline__ void stage_tile(uint32_t kb, uint32_t vb,
                                           const __half* __restrict__ gk_tile,
                                           const __half* __restrict__ gvt_b,
                                           int kt0, int tid)
{
#pragma unroll
    for (int i = 0; i < 4; i++) {
        int idx = tid + i * 256;            // 0..1023
        int row = idx >> 3, g = idx & 7;
        uint32_t dst = kb + (uint32_t)row * 128u + (uint32_t)((g ^ (row & 7)) << 4);
        cp_async16(dst, gk_tile + (size_t)row * 64 + g * 8);
    }
#pragma unroll
    for (int i = 0; i < 4; i++) {
        int idx = tid + i * 256;
        int row = idx >> 4, g = idx & 15;
        uint32_t dst = vb + (uint32_t)row * 256u + (uint32_t)((g ^ (row & 15)) << 4);
        cp_async16(dst, gvt_b + (size_t)row * SEQ + kt0 + g * 8);
    }
}

__global__ void __launch_bounds__(256, 2) attn_mma_kernel(float* __restrict__ out)
{
    extern __shared__ float sm[];
    const uint32_t sb = smem_u32(sm);

    const int tid  = threadIdx.x;
    const int w    = tid >> 5;
    const int lane = tid & 31;
    const int gid  = lane >> 2;
    const int tig  = lane & 3;
    const int wq   = w & 3;          // q-row group (16 rows)
    const int h    = w >> 2;         // key half (64 keys)
    const int b    = blockIdx.y;
    const int q0   = blockIdx.x * 64;
    const int r0   = wq * 16 + gid;  // rows r0, r0+8 (local)

    // ldmatrix lane decomposition
    const int lr = lane & 7;
    const int gi = lane >> 3;
    const uint32_t k_row = (uint32_t)(h * 64 + lr) * 128u;
    const uint32_t kgA = (uint32_t)((gi ^ lr) << 4);
    const uint32_t kgB = (uint32_t)(((gi + 4) ^ lr) << 4);
    const int fl = ((gi >> 1) << 3) + lr;
    const uint32_t v_row = (uint32_t)fl * 256u;

    // ---- Q A-frags straight from fp16 global ----
    const uint32_t* gq = (const uint32_t*)g_q + ((size_t)b * SEQ + q0) * 32;
    uint32_t qa[4][4];
#pragma unroll
    for (int kc = 0; kc < 4; kc++) {
        qa[kc][0] = gq[(size_t)r0 * 32 + kc * 8 + tig];
        qa[kc][1] = gq[(size_t)(r0 + 8) * 32 + kc * 8 + tig];
        qa[kc][2] = gq[(size_t)r0 * 32 + kc * 8 + tig + 4];
        qa[kc][3] = gq[(size_t)(r0 + 8) * 32 + kc * 8 + tig + 4];
    }

    float o[8][4];
#pragma unroll
    for (int ft = 0; ft < 8; ft++)
#pragma unroll
        for (int j = 0; j < 4; j++) o[ft][j] = 0.f;
    float lsum0 = 0.f, lsum1 = 0.f;

    const __half* gk_base = g_k + (size_t)b * SEQ * DF;
    const __half* gvt_b   = g_vt + (size_t)b * DF * SEQ;

    stage_tile(sb, sb + 16384u, gk_base, gvt_b, 0, tid);
    CP_COMMIT();
    stage_tile(sb + KV_BYTES, sb + KV_BYTES + 16384u,
               gk_base + 128 * 64, gvt_b, 128, tid);
    CP_COMMIT();

    for (int t = 0; t < SEQ / 128; t++) {
        if (t + 1 < SEQ / 128) { CP_WAIT1(); } else { CP_WAIT0(); }
        __syncthreads();
        if (t + 2 < SEQ / 128) {
            uint32_t kb = sb + (uint32_t)((t + 2) % 3) * KV_BYTES;
            stage_tile(kb, kb + 16384u,
                       gk_base + (size_t)(t + 2) * 128 * 64, gvt_b,
                       (t + 2) * 128, tid);
            CP_COMMIT();
        }

        const uint32_t Kp = sb + (uint32_t)(t % 3) * KV_BYTES;
        const uint32_t Vp = Kp + 16384u;

#pragma unroll
        for (int j = 0; j < 4; j++) {        // 16-key chunks
            uint32_t pa[4];
#pragma unroll
            for (int hn = 0; hn < 2; hn++) {
                const int nt = j * 2 + hn;
                const uint32_t kbse = Kp + k_row + (uint32_t)nt * 1024u;
                uint32_t ra[4], rb[4];
                ldsm_x4(ra, kbse + kgA);
                ldsm_x4(rb, kbse + kgB);
                float s0[4] = {0.f, 0.f, 0.f, 0.f};
                float s1[4] = {0.f, 0.f, 0.f, 0.f};
                mma_f16(s0, qa[0], ra[0], ra[1]);
                mma_f16(s1, qa[1], ra[2], ra[3]);
                mma_f16(s0, qa[2], rb[0], rb[1]);
                mma_f16(s1, qa[3], rb[2], rb[3]);
                float e0 = __expf(s0[0] + s1[0]);
                float e1 = __expf(s0[1] + s1[1]);
                float e2 = __expf(s0[2] + s1[2]);
                float e3 = __expf(s0[3] + s1[3]);
                lsum0 += e0 + e1;
                lsum1 += e2 + e3;
                pa[hn * 2]     = pack_h2(e0, e1);
                pa[hn * 2 + 1] = pack_h2(e2, e3);
            }
            const uint32_t gx =
                (uint32_t)(((h * 8 + j * 2 + (gi & 1)) ^ fl) << 4);
#pragma unroll
            for (int ftp = 0; ftp < 4; ftp++) {
                uint32_t rv[4];
                ldsm_x4(rv, Vp + v_row + (uint32_t)ftp * 4096u + gx);
                mma_f16(o[ftp * 2],     pa, rv[0], rv[1]);
                mma_f16(o[ftp * 2 + 1], pa, rv[2], rv[3]);
            }
        }
    }

    // ---- quad-reduce l, merge the two key halves through smem ----
    lsum0 += __shfl_xor_sync(0xFFFFFFFF, lsum0, 1);
    lsum0 += __shfl_xor_sync(0xFFFFFFFF, lsum0, 2);
    lsum1 += __shfl_xor_sync(0xFFFFFFFF, lsum1, 1);
    lsum1 += __shfl_xor_sync(0xFFFFFFFF, lsum1, 2);

    __syncthreads();
    float* M  = sm;            // partial O: 64 x 64 fp32
    float* Lm = sm + 4096;     // partial l: 64
    if (h == 1) {
        Lm[r0]     = lsum0;
        Lm[r0 + 8] = lsum1;
#pragma unroll
        for (int ft = 0; ft < 8; ft++) {
            float2 u0, u1;
            u0.x = o[ft][0]; u0.y = o[ft][1];
            u1.x = o[ft][2]; u1.y = o[ft][3];
            *(float2*)(M + (r0)     * 64 + ft * 8 + 2 * tig) = u0;
            *(float2*)(M + (r0 + 8) * 64 + ft * 8 + 2 * tig) = u1;
        }
    }
    __syncthreads();
    if (h == 0) {
        const float inv0 = 1.f / (lsum0 + Lm[r0]);
        const float inv1 = 1.f / (lsum1 + Lm[r0 + 8]);
        float* og0 = out + ((size_t)b * SEQ + q0 + r0) * DF;
        float* og1 = og0 + 8 * DF;
#pragma unroll
        for (int ft = 0; ft < 8; ft++) {
            float2 p0 = *(float2*)(M + (r0)     * 64 + ft * 8 + 2 * tig);
            float2 p1 = *(float2*)(M + (r0 + 8) * 64 + ft * 8 + 2 * tig);
            float2 u0, u1;
            u0.x = (o[ft][0] + p0.x) * inv0;
            u0.y = (o[ft][1] + p0.y) * inv0;
            u1.x = (o[ft][2] + p1.x) * inv1;
            u1.y = (o[ft][3] + p1.y) * inv1;
            *(float2*)(og0 + ft * 8 + 2 * tig) = u0;
            *(float2*)(og1 + ft * 8 + 2 * tig) = u1;
        }
    }
}

// ---------------------------------------------------------------------------
extern "C" void kernel_launch(void* const* d_in, const int* in_sizes, int n_in,
                              void* d_out, int out_size)
{
    const float* queries = (const float*)d_in[0];
    const float* keys    = (const float*)d_in[1];
    const float* values  = (const float*)d_in[2];
    const float* Wq      = (const float*)d_in[3];
    const float* bq      = (const float*)d_in[4];
    const float* Wk      = (const float*)d_in[5];
    const float* bk      = (const float*)d_in[6];
    const float* Wv      = (const float*)d_in[7];
    const float* bv      = (const float*)d_in[8];
    float* out = (float*)d_out;

    static bool attr_set = false;
    if (!attr_set) {
        cudaFuncSetAttribute(proj_tc_kernel,
                             cudaFuncAttributeMaxDynamicSharedMemorySize, P_BYTES);
        cudaFuncSetAttribute(attn_mma_kernel,
                             cudaFuncAttributeMaxDynamicSharedMemorySize, A_BYTES);
        attr_set = true;
    }

    dim3 pgrid(3 * ROWS / 128, 1, 1);
    proj_tc_kernel<<<pgrid, 256, P_BYTES>>>(queries, keys, values,
                                            Wq, bq, Wk, bk, Wv, bv);

    dim3 agrid(SEQ / 64, BATCH, 1);
    attn_mma_kernel<<<agrid, 256, A_BYTES>>>(out);
}